// round 15
// baseline (speedup 1.0000x reference)
#include <cuda_runtime.h>
#include <cuda_bf16.h>
#include <cstdint>
#include <math.h>

#define N_NODES 65536
#define N_GRAPHS 2048
#define NODES_PER_GRAPH 32
#define EDGES_PER_GRAPH 256
#define NEG_SLOPE 0.2f

// ---------------------------------------------------------------------------
// Scratch (device globals; no runtime allocation)
// ---------------------------------------------------------------------------
__device__ float          g_hsd[(size_t)N_NODES * 512];   // GEMM out: [hs|hd]
__device__ __nv_bfloat16  g_a21[(size_t)N_NODES * 256];   // layer1 A: [hi|lo]
__device__ __nv_bfloat16  g_a22[(size_t)N_NODES * 128];   // layer2 A: [hi|lo]
__device__ __nv_bfloat16  g_wt1[(size_t)512 * 384];       // Wt layer1 [n][k'] [hi|lo|hi]
__device__ __nv_bfloat16  g_wt2[(size_t)512 * 192];       // Wt layer2
__device__ float          g_b1[512];
__device__ float          g_b2[512];

// ---------------------------------------------------------------------------
// Conversion kernels.
// A stored [hi|lo]; W stored [hi(all k)|lo(all k)|hi(all k)].
// GEMM chunk schedule pairs: A{hi,hi,lo} x W{hi,lo,hi}  (lo.lo dropped)
// ---------------------------------------------------------------------------
__global__ __launch_bounds__(256) void conv_x_kernel(
    const float* __restrict__ x, __nv_bfloat16* __restrict__ a2)
{
    const int idx = blockIdx.x * 256 + threadIdx.x;   // 0..N_NODES*32-1
    const int row = idx >> 5, c4 = idx & 31;
    float4 v = *(const float4*)&x[(size_t)row * 128 + (c4 << 2)];
    __nv_bfloat16 hx = __float2bfloat16(v.x), hy = __float2bfloat16(v.y);
    __nv_bfloat16 hz = __float2bfloat16(v.z), hw = __float2bfloat16(v.w);
    __nv_bfloat16 lx = __float2bfloat16(v.x - __bfloat162float(hx));
    __nv_bfloat16 ly = __float2bfloat16(v.y - __bfloat162float(hy));
    __nv_bfloat16 lz = __float2bfloat16(v.z - __bfloat162float(hz));
    __nv_bfloat16 lw = __float2bfloat16(v.w - __bfloat162float(hw));
    size_t ob = (size_t)row * 256 + (c4 << 2);
    __nv_bfloat162 t;
    t.x = hx; t.y = hy; *(__nv_bfloat162*)&a2[ob] = t;
    t.x = hz; t.y = hw; *(__nv_bfloat162*)&a2[ob + 2] = t;
    t.x = lx; t.y = ly; *(__nv_bfloat162*)&a2[ob + 128] = t;
    t.x = lz; t.y = lw; *(__nv_bfloat162*)&a2[ob + 130] = t;
}

template <int KIN>   // 128 (layer1) or 64 (layer2)
__global__ __launch_bounds__(256) void conv_w_kernel(
    const float* __restrict__ Ws, const float* __restrict__ bs,
    const float* __restrict__ Wd, const float* __restrict__ bd,
    __nv_bfloat16* __restrict__ Wt, float* __restrict__ ball)
{
    const int idx = blockIdx.x * 256 + threadIdx.x;   // 0..512*3*KIN-1
    const int n = idx / (3 * KIN);
    const int kp = idx % (3 * KIN);
    const int blkk = kp / KIN;      // 0:hi  1:lo  2:hi
    const int k = kp % KIN;
    float w = (n < 256) ? Ws[(size_t)k * 256 + n] : Wd[(size_t)k * 256 + (n - 256)];
    __nv_bfloat16 hi = __float2bfloat16(w);
    __nv_bfloat16 ov = (blkk == 1) ? __float2bfloat16(w - __bfloat162float(hi)) : hi;
    Wt[(size_t)n * (3 * KIN) + kp] = ov;
    if (idx < 512) ball[idx] = (idx < 256) ? bs[idx] : bd[idx - 256];
}

// ---------------------------------------------------------------------------
// Pipelined warp-MMA GEMM with ldmatrix fragments.
// CTA tile 128x128, 8 warps x (32x64), BK=64, cp.async double buffer.
// ---------------------------------------------------------------------------
__device__ __forceinline__ void mma16816(float* c, const uint32_t* a, const uint32_t* b) {
    asm volatile(
        "mma.sync.aligned.m16n8k16.row.col.f32.bf16.bf16.f32 "
        "{%0,%1,%2,%3}, {%4,%5,%6,%7}, {%8,%9}, {%0,%1,%2,%3};"
        : "+f"(c[0]), "+f"(c[1]), "+f"(c[2]), "+f"(c[3])
        : "r"(a[0]), "r"(a[1]), "r"(a[2]), "r"(a[3]), "r"(b[0]), "r"(b[1]));
}
__device__ __forceinline__ void ldsm4(uint32_t* r, uint32_t addr) {
    asm volatile("ldmatrix.sync.aligned.m8n8.x4.shared.b16 {%0,%1,%2,%3}, [%4];"
                 : "=r"(r[0]), "=r"(r[1]), "=r"(r[2]), "=r"(r[3]) : "r"(addr));
}
__device__ __forceinline__ void cp16(void* sdst, const void* gsrc) {
    uint32_t d = (uint32_t)__cvta_generic_to_shared(sdst);
    asm volatile("cp.async.cg.shared.global [%0], [%1], 16;" :: "r"(d), "l"(gsrc));
}
#define CP_COMMIT() asm volatile("cp.async.commit_group;")

#define GLDS 72                    // padded smem stride (bf16 elems)
#define TILE_E (128 * GLDS)        // elems per tile
#define STAGE_E (2 * TILE_E)       // A + B per stage
#define TILE_B (TILE_E * 2)        // bytes
#define STAGE_B (STAGE_E * 2)
#define GEMM_SMEM (2 * STAGE_B + 512)

template <int NC>
__device__ __forceinline__ int a_off(int c) {
    if (NC == 6) { const int t[6] = {0, 64, 0, 64, 128, 192}; return t[c]; }
    else         { const int t[3] = {0, 0, 64};               return t[c]; }
}

template <int NC, int LDA, int LDW>
__global__ __launch_bounds__(256, 2) void gemm_mma_kernel(
    const __nv_bfloat16* __restrict__ A, const __nv_bfloat16* __restrict__ W,
    const float* __restrict__ ball, float* __restrict__ out)
{
    extern __shared__ __align__(16) __nv_bfloat16 smg[];
    float* s_bias = (float*)(smg + 2 * STAGE_E);
    const uint32_t sb = (uint32_t)__cvta_generic_to_shared(smg);

    const int tid = threadIdx.x, wid = tid >> 5, lane = tid & 31;
    const int m0 = blockIdx.x * 128;
    const int n0 = blockIdx.y * 128;
    const int wr = wid & 3;        // warp row: 4 x 32 rows
    const int wc = wid >> 2;       // warp col: 2 x 64 cols

    if (tid < 128) s_bias[tid] = ball[n0 + tid];

    float acc[2][8][4];
#pragma unroll
    for (int mt = 0; mt < 2; mt++)
#pragma unroll
        for (int nt = 0; nt < 8; nt++)
#pragma unroll
            for (int q = 0; q < 4; q++) acc[mt][nt][q] = 0.f;

    const int lr = tid >> 3;
    const int lc = (tid & 7) * 8;

    // per-lane ldmatrix offsets (bytes)
    const uint32_t a_lo = (uint32_t)(((wr * 32 + (lane & 15)) * GLDS + ((lane >> 4) << 3)) * 2);
    const uint32_t b_lo = (uint32_t)(((wc * 64 + ((lane >> 4) << 3) + (lane & 7)) * GLDS
                                      + (((lane >> 3) & 1) << 3)) * 2);

    // prologue: stage 0
#pragma unroll
    for (int i = 0; i < 4; i++) {
        const int r = lr + i * 32;
        cp16(&smg[r * GLDS + lc], &A[(size_t)(m0 + r) * LDA + a_off<NC>(0) + lc]);
        cp16(&smg[TILE_E + r * GLDS + lc], &W[(size_t)(n0 + r) * LDW + lc]);
    }
    CP_COMMIT();

#pragma unroll
    for (int c = 0; c < NC; c++) {
        const int buf = c & 1;
        if (c + 1 < NC) {
            const int ka = a_off<NC>(c + 1);
            const int kw = (c + 1) * 64;
            __nv_bfloat16* sa = smg + (buf ^ 1) * STAGE_E;
#pragma unroll
            for (int i = 0; i < 4; i++) {
                const int r = lr + i * 32;
                cp16(&sa[r * GLDS + lc], &A[(size_t)(m0 + r) * LDA + ka + lc]);
                cp16(&sa[TILE_E + r * GLDS + lc], &W[(size_t)(n0 + r) * LDW + kw + lc]);
            }
            CP_COMMIT();
            asm volatile("cp.async.wait_group 1;");
        } else {
            asm volatile("cp.async.wait_group 0;");
        }
        __syncthreads();

        const uint32_t abase = sb + buf * STAGE_B + a_lo;
        const uint32_t bbase = sb + buf * STAGE_B + TILE_B + b_lo;
#pragma unroll
        for (int ks = 0; ks < 4; ks++) {
            uint32_t a[2][4], b[8][2];
            const uint32_t ko = ks * 32;
#pragma unroll
            for (int mt = 0; mt < 2; mt++)
                ldsm4(a[mt], abase + mt * (16 * GLDS * 2) + ko);
#pragma unroll
            for (int ntp = 0; ntp < 4; ntp++) {
                uint32_t t[4];
                ldsm4(t, bbase + ntp * (16 * GLDS * 2) + ko);
                b[2 * ntp][0] = t[0]; b[2 * ntp][1] = t[1];
                b[2 * ntp + 1][0] = t[2]; b[2 * ntp + 1][1] = t[3];
            }
#pragma unroll
            for (int mt = 0; mt < 2; mt++)
#pragma unroll
                for (int nt = 0; nt < 8; nt++)
                    mma16816(acc[mt][nt], a[mt], b[nt]);
        }
        __syncthreads();
    }

    // epilogue
    const int cr = lane >> 2;
    const int cc = (lane & 3) * 2;
#pragma unroll
    for (int mt = 0; mt < 2; mt++) {
        const int row = m0 + wr * 32 + mt * 16 + cr;
#pragma unroll
        for (int nt = 0; nt < 8; nt++) {
            const int col = wc * 64 + nt * 8 + cc;
            float2 v0, v1;
            v0.x = acc[mt][nt][0] + s_bias[col];
            v0.y = acc[mt][nt][1] + s_bias[col + 1];
            v1.x = acc[mt][nt][2] + s_bias[col];
            v1.y = acc[mt][nt][3] + s_bias[col + 1];
            *(float2*)&out[(size_t)row * 512 + n0 + col] = v0;
            *(float2*)&out[(size_t)(row + 8) * 512 + n0 + col] = v1;
        }
    }
}

// ---------------------------------------------------------------------------
// Per-graph GATv2 attention + head-max (edge-parallel).
// One CTA per graph, 256 threads.
// Logit pass uses edge-rotated d-indexing to break smem bank conflicts.
// POOL=false: writes split-bf16 [hi|lo] (128-wide) to a2out.
// POOL=true: global attention pooling.
// ---------------------------------------------------------------------------
__device__ __forceinline__ void atomicMaxF(float* addr, float v) {
    if (v >= 0.f) atomicMax((int*)addr, __float_as_int(v));
    else          atomicMin((unsigned int*)addr, __float_as_uint(v));
}

#define GAT_SMEM 79872

template <bool POOL>
__global__ __launch_bounds__(256) void gat_kernel(
    const float* __restrict__ hsd,
    const int* __restrict__ src, const int* __restrict__ dst,
    const float* __restrict__ attn,
    __nv_bfloat16* __restrict__ a2out,
    const float* __restrict__ Wg, const float* __restrict__ bg,
    float* __restrict__ pool_out)
{
    extern __shared__ __align__(16) float sm[];
    float* s_hs    = sm;             // [(n*4+h)*68 + d]  8704
    float* s_hd    = sm + 8704;      // same layout       8704  (reused as s_hm)
    float* s_logit = sm + 17408;     // 1024
    float* s_attn  = sm + 18432;     // [h*68+d] 272
    float* s_nmax  = sm + 18704;     // 128
    float* s_nden  = sm + 18832;     // 128
    float* s_wg    = sm + 18960;     // 64
    float* s_alpha = sm + 19024;     // 32
    float* s_bg    = sm + 19056;     // 4 (pad to 19072)
    int* s_src = (int*)(sm + 19072); // 256
    int* s_dst = s_src + 256;
    int* s_eid = s_dst + 256;
    int* s_cnt = s_eid + 256;        // 32
    int* s_ofs = s_cnt + 32;
    int* s_cur = s_ofs + 32;

    const int tid = threadIdx.x;
    const int bid = blockIdx.x;
    const int base = bid * NODES_PER_GRAPH;
    const int lane = tid & 31;

    // ---- load phase ----
    {
        const float4* g4 = (const float4*)(hsd + (size_t)base * 512);
#pragma unroll
        for (int i = 0; i < 16; i++) {
            int g = tid + (i << 8);
            int n = g >> 7, c4 = g & 127;
            float4 v = g4[g];
            int col = c4 << 2;
            int h = (col >> 6) & 3;
            int d = col & 63;
            float* dp = ((col < 256) ? s_hs : s_hd) + ((n << 2) + h) * 68 + d;
            *(float4*)dp = v;
        }
    }
    { int h = tid >> 6, d = tid & 63; s_attn[h * 68 + d] = attn[tid]; }
    if (POOL) {
        if (tid < 64) s_wg[tid] = Wg[tid];
        if (tid == 0) s_bg[0] = bg[0];
    }
    s_src[tid] = src[bid * EDGES_PER_GRAPH + tid] - base;
    s_dst[tid] = dst[bid * EDGES_PER_GRAPH + tid] - base;
    if (tid < 128) { s_nmax[tid] = -INFINITY; s_nden[tid] = 0.f; }
    if (tid < 32)  { s_cnt[tid] = 0; }
    __syncthreads();

    // ---- CSR counts + edge logits + per-(dst,head) max ----
    atomicAdd(&s_cnt[s_dst[tid]], 1);
#pragma unroll
    for (int p = tid; p < 1024; p += 256) {
        const int e = p >> 2, h = p & 3;
        const float4* vs = (const float4*)(s_hs + ((s_src[e] << 2) + h) * 68);
        const float4* vd = (const float4*)(s_hd + ((s_dst[e] << 2) + h) * 68);
        const float4* va = (const float4*)(s_attn + h * 68);
        float ax = 0.f, ay = 0.f, az = 0.f, aw = 0.f;
        const int rot = e & 15;   // edge-rotated start -> breaks bank conflicts
#pragma unroll
        for (int ii = 0; ii < 16; ii++) {
            const int i = (ii + rot) & 15;
            float4 a = vs[i], b = vd[i], w = va[i];
            float v0 = a.x + b.x; v0 = fmaxf(v0, NEG_SLOPE * v0); ax = fmaf(w.x, v0, ax);
            float v1 = a.y + b.y; v1 = fmaxf(v1, NEG_SLOPE * v1); ay = fmaf(w.y, v1, ay);
            float v2 = a.z + b.z; v2 = fmaxf(v2, NEG_SLOPE * v2); az = fmaf(w.z, v2, az);
            float v3 = a.w + b.w; v3 = fmaxf(v3, NEG_SLOPE * v3); aw = fmaf(w.w, v3, aw);
        }
        const float lg = (ax + ay) + (az + aw);
        s_logit[p] = lg;
        atomicMaxF(&s_nmax[(s_dst[e] << 2) + h], lg);
    }
    __syncthreads();

    // ---- CSR offsets (exclusive scan over 32 counts) ----
    if (tid < 32) {
        const int c = s_cnt[tid];
        int x = c;
#pragma unroll
        for (int off = 1; off < 32; off <<= 1) {
            int y = __shfl_up_sync(0xffffffffu, x, off);
            if (lane >= off) x += y;
        }
        s_ofs[tid] = x - c;
        s_cur[tid] = x - c;
    }
    __syncthreads();

    // ---- CSR scatter + exp & denominator ----
    {
        const int slot = atomicAdd(&s_cur[s_dst[tid]], 1);
        s_eid[slot] = tid;
    }
#pragma unroll
    for (int p = tid; p < 1024; p += 256) {
        const int e = p >> 2, h = p & 3;
        const int idx = (s_dst[e] << 2) + h;
        const float ex = __expf(s_logit[p] - s_nmax[idx]);
        s_logit[p] = ex;
        atomicAdd(&s_nden[idx], ex);
    }
    __syncthreads();

    // ---- aggregation (per (node, d4), alpha = exp/den folded in) + head max ----
#pragma unroll
    for (int o = tid; o < 512; o += 256) {
        const int n = o >> 4, q = o & 15;
        float4 a0 = {0, 0, 0, 0}, a1 = {0, 0, 0, 0}, a2v = {0, 0, 0, 0}, a3 = {0, 0, 0, 0};
        const int beg = s_ofs[n];
        const int end = beg + s_cnt[n];
        for (int i = beg; i < end; i++) {
            const int e = s_eid[i];
            const float4 w = *(const float4*)&s_logit[e << 2];
            const int sbi = s_src[e] << 2;
            const float4 h0 = ((const float4*)(s_hs + (sbi + 0) * 68))[q];
            const float4 h1 = ((const float4*)(s_hs + (sbi + 1) * 68))[q];
            const float4 h2 = ((const float4*)(s_hs + (sbi + 2) * 68))[q];
            const float4 h3 = ((const float4*)(s_hs + (sbi + 3) * 68))[q];
            a0.x = fmaf(w.x, h0.x, a0.x); a0.y = fmaf(w.x, h0.y, a0.y);
            a0.z = fmaf(w.x, h0.z, a0.z); a0.w = fmaf(w.x, h0.w, a0.w);
            a1.x = fmaf(w.y, h1.x, a1.x); a1.y = fmaf(w.y, h1.y, a1.y);
            a1.z = fmaf(w.y, h1.z, a1.z); a1.w = fmaf(w.y, h1.w, a1.w);
            a2v.x = fmaf(w.z, h2.x, a2v.x); a2v.y = fmaf(w.z, h2.y, a2v.y);
            a2v.z = fmaf(w.z, h2.z, a2v.z); a2v.w = fmaf(w.z, h2.w, a2v.w);
            a3.x = fmaf(w.w, h3.x, a3.x); a3.y = fmaf(w.w, h3.y, a3.y);
            a3.z = fmaf(w.w, h3.z, a3.z); a3.w = fmaf(w.w, h3.w, a3.w);
        }
        // fold softmax denominators (guard zero in-degree)
        float d0 = s_nden[(n << 2) + 0]; d0 = (d0 == 0.f) ? 1.f : d0;
        float d1 = s_nden[(n << 2) + 1]; d1 = (d1 == 0.f) ? 1.f : d1;
        float d2 = s_nden[(n << 2) + 2]; d2 = (d2 == 0.f) ? 1.f : d2;
        float d3 = s_nden[(n << 2) + 3]; d3 = (d3 == 0.f) ? 1.f : d3;
        const float r0 = 1.f / d0, r1 = 1.f / d1, r2 = 1.f / d2, r3 = 1.f / d3;
        float4 m;
        m.x = fmaxf(fmaxf(a0.x * r0, a1.x * r1), fmaxf(a2v.x * r2, a3.x * r3));
        m.y = fmaxf(fmaxf(a0.y * r0, a1.y * r1), fmaxf(a2v.y * r2, a3.y * r3));
        m.z = fmaxf(fmaxf(a0.z * r0, a1.z * r1), fmaxf(a2v.z * r2, a3.z * r3));
        m.w = fmaxf(fmaxf(a0.w * r0, a1.w * r1), fmaxf(a2v.w * r2, a3.w * r3));
        if (POOL) {
            *(float4*)&s_hd[n * 68 + (q << 2)] = m;   // s_hm overlay
        } else {
            __nv_bfloat16 hx = __float2bfloat16(m.x), hy = __float2bfloat16(m.y);
            __nv_bfloat16 hz = __float2bfloat16(m.z), hw = __float2bfloat16(m.w);
            __nv_bfloat16 lx = __float2bfloat16(m.x - __bfloat162float(hx));
            __nv_bfloat16 ly = __float2bfloat16(m.y - __bfloat162float(hy));
            __nv_bfloat16 lz = __float2bfloat16(m.z - __bfloat162float(hz));
            __nv_bfloat16 lw = __float2bfloat16(m.w - __bfloat162float(hw));
            size_t ob = (size_t)(base + n) * 128 + (q << 2);
            __nv_bfloat162 t;
            t.x = hx; t.y = hy; *(__nv_bfloat162*)&a2out[ob] = t;
            t.x = hz; t.y = hw; *(__nv_bfloat162*)&a2out[ob + 2] = t;
            t.x = lx; t.y = ly; *(__nv_bfloat162*)&a2out[ob + 64] = t;
            t.x = lz; t.y = lw; *(__nv_bfloat162*)&a2out[ob + 66] = t;
        }
    }

    if (POOL) {
        __syncthreads();
        if (tid < 32) {
            float g = s_bg[0];
#pragma unroll 8
            for (int dd = 0; dd < 64; dd++) {
                const int d = (dd + tid) & 63;
                g = fmaf(s_wg[d], s_hd[tid * 68 + d], g);
            }
            float mx = g;
#pragma unroll
            for (int off = 16; off > 0; off >>= 1)
                mx = fmaxf(mx, __shfl_xor_sync(0xffffffffu, mx, off));
            const float ex = __expf(g - mx);
            float den = ex;
#pragma unroll
            for (int off = 16; off > 0; off >>= 1)
                den += __shfl_xor_sync(0xffffffffu, den, off);
            s_alpha[tid] = ex / den;
        }
        __syncthreads();
        if (tid < 64) {
            float acc = 0.f;
#pragma unroll
            for (int n = 0; n < 32; n++) acc = fmaf(s_alpha[n], s_hd[n * 68 + tid], acc);
            pool_out[(size_t)bid * 64 + tid] = acc;
        }
    }
}

// ---------------------------------------------------------------------------
extern "C" void kernel_launch(void* const* d_in, const int* in_sizes, int n_in,
                              void* d_out, int out_size)
{
    const float* x   = (const float*)d_in[0];
    const int* src   = (const int*)d_in[1];
    const int* dst   = (const int*)d_in[2];
    const float* W1s = (const float*)d_in[4];
    const float* b1s = (const float*)d_in[5];
    const float* W1d = (const float*)d_in[6];
    const float* b1d = (const float*)d_in[7];
    const float* a1  = (const float*)d_in[8];
    const float* W2s = (const float*)d_in[9];
    const float* b2s = (const float*)d_in[10];
    const float* W2d = (const float*)d_in[11];
    const float* b2d = (const float*)d_in[12];
    const float* a2  = (const float*)d_in[13];
    const float* Wg  = (const float*)d_in[14];
    const float* bg  = (const float*)d_in[15];
    float* out = (float*)d_out;

    cudaFuncSetAttribute(gat_kernel<false>, cudaFuncAttributeMaxDynamicSharedMemorySize, GAT_SMEM);
    cudaFuncSetAttribute(gat_kernel<true>,  cudaFuncAttributeMaxDynamicSharedMemorySize, GAT_SMEM);
    cudaFuncSetAttribute(gemm_mma_kernel<6, 256, 384>, cudaFuncAttributeMaxDynamicSharedMemorySize, GEMM_SMEM);
    cudaFuncSetAttribute(gemm_mma_kernel<3, 128, 192>, cudaFuncAttributeMaxDynamicSharedMemorySize, GEMM_SMEM);

    float* hsd;  __nv_bfloat16* a21; __nv_bfloat16* a22;
    __nv_bfloat16* wt1; __nv_bfloat16* wt2; float* bb1; float* bb2;
    cudaGetSymbolAddress((void**)&hsd, g_hsd);
    cudaGetSymbolAddress((void**)&a21, g_a21);
    cudaGetSymbolAddress((void**)&a22, g_a22);
    cudaGetSymbolAddress((void**)&wt1, g_wt1);
    cudaGetSymbolAddress((void**)&wt2, g_wt2);
    cudaGetSymbolAddress((void**)&bb1, g_b1);
    cudaGetSymbolAddress((void**)&bb2, g_b2);

    conv_x_kernel<<<(N_NODES * 32) / 256, 256>>>(x, a21);
    conv_w_kernel<128><<<(512 * 384) / 256, 256>>>(W1s, b1s, W1d, b1d, wt1, bb1);
    conv_w_kernel<64><<<(512 * 192) / 256, 256>>>(W2s, b2s, W2d, b2d, wt2, bb2);

    dim3 gg(N_NODES / 128, 4);
    gemm_mma_kernel<6, 256, 384><<<gg, 256, GEMM_SMEM>>>(a21, wt1, bb1, hsd);
    gat_kernel<false><<<N_GRAPHS, 256, GAT_SMEM>>>(hsd, src, dst, a1, a22,
                                                   nullptr, nullptr, nullptr);
    gemm_mma_kernel<3, 128, 192><<<gg, 256, GEMM_SMEM>>>(a22, wt2, bb2, hsd);
    gat_kernel<true><<<N_GRAPHS, 256, GAT_SMEM>>>(hsd, src, dst, a2, nullptr,
                                                  Wg, bg, out);
}

// round 16
// speedup vs baseline: 1.1579x; 1.1579x over previous
#include <cuda_runtime.h>
#include <cuda_bf16.h>
#include <cstdint>
#include <math.h>

#define N_NODES 65536
#define N_GRAPHS 2048
#define NODES_PER_GRAPH 32
#define EDGES_PER_GRAPH 256
#define NEG_SLOPE 0.2f

// ---------------------------------------------------------------------------
// Scratch (device globals; no runtime allocation)
// ---------------------------------------------------------------------------
__device__ float          g_hsd[(size_t)N_NODES * 512];   // GEMM out: [hs|hd]
__device__ __nv_bfloat16  g_a21[(size_t)N_NODES * 256];   // layer1 A: [hi|lo]
__device__ __nv_bfloat16  g_a22[(size_t)N_NODES * 128];   // layer2 A: [hi|lo]
__device__ __nv_bfloat16  g_wt1[(size_t)512 * 384];       // Wt layer1 [n][k'] [hi|lo|hi]
__device__ __nv_bfloat16  g_wt2[(size_t)512 * 192];       // Wt layer2
__device__ float          g_b1[512];
__device__ float          g_b2[512];

// ---------------------------------------------------------------------------
// Conversion kernels.
// A stored [hi|lo]; W stored [hi(all k)|lo(all k)|hi(all k)].
// GEMM chunk schedule pairs: A{hi,hi,lo} x W{hi,lo,hi}  (lo.lo dropped)
// ---------------------------------------------------------------------------
__global__ __launch_bounds__(256) void conv_x_kernel(
    const float* __restrict__ x, __nv_bfloat16* __restrict__ a2)
{
    const int idx = blockIdx.x * 256 + threadIdx.x;   // 0..N_NODES*32-1
    const int row = idx >> 5, c4 = idx & 31;
    float4 v = *(const float4*)&x[(size_t)row * 128 + (c4 << 2)];
    __nv_bfloat16 hx = __float2bfloat16(v.x), hy = __float2bfloat16(v.y);
    __nv_bfloat16 hz = __float2bfloat16(v.z), hw = __float2bfloat16(v.w);
    __nv_bfloat16 lx = __float2bfloat16(v.x - __bfloat162float(hx));
    __nv_bfloat16 ly = __float2bfloat16(v.y - __bfloat162float(hy));
    __nv_bfloat16 lz = __float2bfloat16(v.z - __bfloat162float(hz));
    __nv_bfloat16 lw = __float2bfloat16(v.w - __bfloat162float(hw));
    size_t ob = (size_t)row * 256 + (c4 << 2);
    __nv_bfloat162 t;
    t.x = hx; t.y = hy; *(__nv_bfloat162*)&a2[ob] = t;
    t.x = hz; t.y = hw; *(__nv_bfloat162*)&a2[ob + 2] = t;
    t.x = lx; t.y = ly; *(__nv_bfloat162*)&a2[ob + 128] = t;
    t.x = lz; t.y = lw; *(__nv_bfloat162*)&a2[ob + 130] = t;
}

template <int KIN>   // 128 (layer1) or 64 (layer2)
__global__ __launch_bounds__(256) void conv_w_kernel(
    const float* __restrict__ Ws, const float* __restrict__ bs,
    const float* __restrict__ Wd, const float* __restrict__ bd,
    __nv_bfloat16* __restrict__ Wt, float* __restrict__ ball)
{
    const int idx = blockIdx.x * 256 + threadIdx.x;   // 0..512*3*KIN-1
    const int n = idx / (3 * KIN);
    const int kp = idx % (3 * KIN);
    const int blkk = kp / KIN;      // 0:hi  1:lo  2:hi
    const int k = kp % KIN;
    float w = (n < 256) ? Ws[(size_t)k * 256 + n] : Wd[(size_t)k * 256 + (n - 256)];
    __nv_bfloat16 hi = __float2bfloat16(w);
    __nv_bfloat16 ov = (blkk == 1) ? __float2bfloat16(w - __bfloat162float(hi)) : hi;
    Wt[(size_t)n * (3 * KIN) + kp] = ov;
    if (idx < 512) ball[idx] = (idx < 256) ? bs[idx] : bd[idx - 256];
}

// ---------------------------------------------------------------------------
// Pipelined warp-MMA GEMM with ldmatrix fragments.
// CTA tile 128x128, 8 warps x (32x64), BK=64.
// 3-stage cp.async pipeline, ONE __syncthreads per chunk.
// ---------------------------------------------------------------------------
__device__ __forceinline__ void mma16816(float* c, const uint32_t* a, const uint32_t* b) {
    asm volatile(
        "mma.sync.aligned.m16n8k16.row.col.f32.bf16.bf16.f32 "
        "{%0,%1,%2,%3}, {%4,%5,%6,%7}, {%8,%9}, {%0,%1,%2,%3};"
        : "+f"(c[0]), "+f"(c[1]), "+f"(c[2]), "+f"(c[3])
        : "r"(a[0]), "r"(a[1]), "r"(a[2]), "r"(a[3]), "r"(b[0]), "r"(b[1]));
}
__device__ __forceinline__ void ldsm4(uint32_t* r, uint32_t addr) {
    asm volatile("ldmatrix.sync.aligned.m8n8.x4.shared.b16 {%0,%1,%2,%3}, [%4];"
                 : "=r"(r[0]), "=r"(r[1]), "=r"(r[2]), "=r"(r[3]) : "r"(addr));
}
__device__ __forceinline__ void cp16(void* sdst, const void* gsrc) {
    uint32_t d = (uint32_t)__cvta_generic_to_shared(sdst);
    asm volatile("cp.async.cg.shared.global [%0], [%1], 16;" :: "r"(d), "l"(gsrc));
}
#define CP_COMMIT() asm volatile("cp.async.commit_group;")

#define GLDS 72                    // padded smem stride (bf16 elems)
#define TILE_E (128 * GLDS)        // elems per tile
#define STAGE_E (2 * TILE_E)       // A + B per stage
#define TILE_B (TILE_E * 2)        // bytes
#define STAGE_B (STAGE_E * 2)
#define NSTAGE 3
#define GEMM_SMEM (NSTAGE * STAGE_B + 512)

template <int NC>
__device__ __forceinline__ int a_off(int c) {
    if (NC == 6) { const int t[6] = {0, 64, 0, 64, 128, 192}; return t[c]; }
    else         { const int t[3] = {0, 0, 64};               return t[c]; }
}

template <int NC, int LDA, int LDW>
__global__ __launch_bounds__(256, 2) void gemm_mma_kernel(
    const __nv_bfloat16* __restrict__ A, const __nv_bfloat16* __restrict__ W,
    const float* __restrict__ ball, float* __restrict__ out)
{
    extern __shared__ __align__(16) __nv_bfloat16 smg[];
    float* s_bias = (float*)(smg + NSTAGE * STAGE_E);
    const uint32_t sb = (uint32_t)__cvta_generic_to_shared(smg);

    const int tid = threadIdx.x, wid = tid >> 5, lane = tid & 31;
    const int m0 = blockIdx.x * 128;
    const int n0 = blockIdx.y * 128;
    const int wr = wid & 3;        // warp row: 4 x 32 rows
    const int wc = wid >> 2;       // warp col: 2 x 64 cols

    if (tid < 128) s_bias[tid] = ball[n0 + tid];

    float acc[2][8][4];
#pragma unroll
    for (int mt = 0; mt < 2; mt++)
#pragma unroll
        for (int nt = 0; nt < 8; nt++)
#pragma unroll
            for (int q = 0; q < 4; q++) acc[mt][nt][q] = 0.f;

    const int lr = tid >> 3;
    const int lc = (tid & 7) * 8;

    // per-lane ldmatrix offsets (bytes)
    const uint32_t a_lo = (uint32_t)(((wr * 32 + (lane & 15)) * GLDS + ((lane >> 4) << 3)) * 2);
    const uint32_t b_lo = (uint32_t)(((wc * 64 + ((lane >> 4) << 3) + (lane & 7)) * GLDS
                                      + (((lane >> 3) & 1) << 3)) * 2);

    // prologue: stages 0 and 1
#pragma unroll
    for (int i = 0; i < 4; i++) {
        const int r = lr + i * 32;
        cp16(&smg[r * GLDS + lc], &A[(size_t)(m0 + r) * LDA + a_off<NC>(0) + lc]);
        cp16(&smg[TILE_E + r * GLDS + lc], &W[(size_t)(n0 + r) * LDW + lc]);
    }
    CP_COMMIT();
#pragma unroll
    for (int i = 0; i < 4; i++) {
        const int r = lr + i * 32;
        cp16(&smg[STAGE_E + r * GLDS + lc], &A[(size_t)(m0 + r) * LDA + a_off<NC>(1) + lc]);
        cp16(&smg[STAGE_E + TILE_E + r * GLDS + lc], &W[(size_t)(n0 + r) * LDW + 64 + lc]);
    }
    CP_COMMIT();

#pragma unroll
    for (int c = 0; c < NC; c++) {
        const int buf = c % NSTAGE;
        if (c + 1 < NC) asm volatile("cp.async.wait_group 1;");
        else            asm volatile("cp.async.wait_group 0;");
        __syncthreads();

        const uint32_t abase = sb + buf * STAGE_B + a_lo;
        const uint32_t bbase = sb + buf * STAGE_B + TILE_B + b_lo;
#pragma unroll
        for (int ks = 0; ks < 4; ks++) {
            uint32_t a[2][4], b[8][2];
            const uint32_t ko = ks * 32;
#pragma unroll
            for (int mt = 0; mt < 2; mt++)
                ldsm4(a[mt], abase + mt * (16 * GLDS * 2) + ko);
#pragma unroll
            for (int ntp = 0; ntp < 4; ntp++) {
                uint32_t t[4];
                ldsm4(t, bbase + ntp * (16 * GLDS * 2) + ko);
                b[2 * ntp][0] = t[0]; b[2 * ntp][1] = t[1];
                b[2 * ntp + 1][0] = t[2]; b[2 * ntp + 1][1] = t[3];
            }
#pragma unroll
            for (int mt = 0; mt < 2; mt++)
#pragma unroll
                for (int nt = 0; nt < 8; nt++)
                    mma16816(acc[mt][nt], a[mt], b[nt]);
        }

        if (c + 2 < NC) {
            const int nb = (c + 2) % NSTAGE;
            const int ka = a_off<NC>(c + 2);
            const int kw = (c + 2) * 64;
            __nv_bfloat16* sa = smg + nb * STAGE_E;
#pragma unroll
            for (int i = 0; i < 4; i++) {
                const int r = lr + i * 32;
                cp16(&sa[r * GLDS + lc], &A[(size_t)(m0 + r) * LDA + ka + lc]);
                cp16(&sa[TILE_E + r * GLDS + lc], &W[(size_t)(n0 + r) * LDW + kw + lc]);
            }
            CP_COMMIT();
        }
    }

    // epilogue
    const int cr = lane >> 2;
    const int cc = (lane & 3) * 2;
#pragma unroll
    for (int mt = 0; mt < 2; mt++) {
        const int row = m0 + wr * 32 + mt * 16 + cr;
#pragma unroll
        for (int nt = 0; nt < 8; nt++) {
            const int col = wc * 64 + nt * 8 + cc;
            float2 v0, v1;
            v0.x = acc[mt][nt][0] + s_bias[col];
            v0.y = acc[mt][nt][1] + s_bias[col + 1];
            v1.x = acc[mt][nt][2] + s_bias[col];
            v1.y = acc[mt][nt][3] + s_bias[col + 1];
            *(float2*)&out[(size_t)row * 512 + n0 + col] = v0;
            *(float2*)&out[(size_t)(row + 8) * 512 + n0 + col] = v1;
        }
    }
}

// ---------------------------------------------------------------------------
// Per-graph GATv2 attention + head-max (edge-parallel, R10 measured design).
// One CTA per graph, 256 threads.
// POOL=false: writes split-bf16 [hi|lo] (128-wide) to a2out.
// POOL=true: global attention pooling.
// ---------------------------------------------------------------------------
__device__ __forceinline__ void atomicMaxF(float* addr, float v) {
    if (v >= 0.f) atomicMax((int*)addr, __float_as_int(v));
    else          atomicMin((unsigned int*)addr, __float_as_uint(v));
}

#define GAT_SMEM 79872

template <bool POOL>
__global__ __launch_bounds__(256) void gat_kernel(
    const float* __restrict__ hsd,
    const int* __restrict__ src, const int* __restrict__ dst,
    const float* __restrict__ attn,
    __nv_bfloat16* __restrict__ a2out,
    const float* __restrict__ Wg, const float* __restrict__ bg,
    float* __restrict__ pool_out)
{
    extern __shared__ __align__(16) float sm[];
    float* s_hs    = sm;             // [(n*4+h)*68 + d]  8704
    float* s_hd    = sm + 8704;      // same layout       8704  (reused as s_hm)
    float* s_logit = sm + 17408;     // 1024
    float* s_attn  = sm + 18432;     // [h*68+d] 272
    float* s_nmax  = sm + 18704;     // 128
    float* s_nden  = sm + 18832;     // 128
    float* s_wg    = sm + 18960;     // 64
    float* s_alpha = sm + 19024;     // 32
    float* s_bg    = sm + 19056;     // 4 (pad to 19072)
    int* s_src = (int*)(sm + 19072); // 256
    int* s_dst = s_src + 256;
    int* s_eid = s_dst + 256;
    int* s_cnt = s_eid + 256;        // 32
    int* s_ofs = s_cnt + 32;
    int* s_cur = s_ofs + 32;

    const int tid = threadIdx.x;
    const int bid = blockIdx.x;
    const int base = bid * NODES_PER_GRAPH;
    const int lane = tid & 31;

    // ---- load phase ----
    {
        const float4* g4 = (const float4*)(hsd + (size_t)base * 512);
#pragma unroll
        for (int i = 0; i < 16; i++) {
            int g = tid + (i << 8);
            int n = g >> 7, c4 = g & 127;
            float4 v = g4[g];
            int col = c4 << 2;
            int h = (col >> 6) & 3;
            int d = col & 63;
            float* dp = ((col < 256) ? s_hs : s_hd) + ((n << 2) + h) * 68 + d;
            *(float4*)dp = v;
        }
    }
    { int h = tid >> 6, d = tid & 63; s_attn[h * 68 + d] = attn[tid]; }
    if (POOL) {
        if (tid < 64) s_wg[tid] = Wg[tid];
        if (tid == 0) s_bg[0] = bg[0];
    }
    s_src[tid] = src[bid * EDGES_PER_GRAPH + tid] - base;
    s_dst[tid] = dst[bid * EDGES_PER_GRAPH + tid] - base;
    if (tid < 128) { s_nmax[tid] = -INFINITY; s_nden[tid] = 0.f; }
    if (tid < 32)  { s_cnt[tid] = 0; }
    __syncthreads();

    // ---- CSR counts + edge logits + per-(dst,head) max ----
    atomicAdd(&s_cnt[s_dst[tid]], 1);
#pragma unroll
    for (int p = tid; p < 1024; p += 256) {
        const int e = p >> 2, h = p & 3;
        const float4* vs = (const float4*)(s_hs + ((s_src[e] << 2) + h) * 68);
        const float4* vd = (const float4*)(s_hd + ((s_dst[e] << 2) + h) * 68);
        const float4* va = (const float4*)(s_attn + h * 68);
        float ax = 0.f, ay = 0.f, az = 0.f, aw = 0.f;
#pragma unroll
        for (int i = 0; i < 16; i++) {
            float4 a = vs[i], b = vd[i], w = va[i];
            float v0 = a.x + b.x; v0 = fmaxf(v0, NEG_SLOPE * v0); ax = fmaf(w.x, v0, ax);
            float v1 = a.y + b.y; v1 = fmaxf(v1, NEG_SLOPE * v1); ay = fmaf(w.y, v1, ay);
            float v2 = a.z + b.z; v2 = fmaxf(v2, NEG_SLOPE * v2); az = fmaf(w.z, v2, az);
            float v3 = a.w + b.w; v3 = fmaxf(v3, NEG_SLOPE * v3); aw = fmaf(w.w, v3, aw);
        }
        const float lg = (ax + ay) + (az + aw);
        s_logit[p] = lg;
        atomicMaxF(&s_nmax[(s_dst[e] << 2) + h], lg);
    }
    __syncthreads();

    // ---- CSR offsets (exclusive scan over 32 counts) ----
    if (tid < 32) {
        const int c = s_cnt[tid];
        int x = c;
#pragma unroll
        for (int off = 1; off < 32; off <<= 1) {
            int y = __shfl_up_sync(0xffffffffu, x, off);
            if (lane >= off) x += y;
        }
        s_ofs[tid] = x - c;
        s_cur[tid] = x - c;
    }
    __syncthreads();

    // ---- CSR scatter + exp & denominator ----
    {
        const int slot = atomicAdd(&s_cur[s_dst[tid]], 1);
        s_eid[slot] = tid;
    }
#pragma unroll
    for (int p = tid; p < 1024; p += 256) {
        const int e = p >> 2, h = p & 3;
        const int idx = (s_dst[e] << 2) + h;
        const float ex = __expf(s_logit[p] - s_nmax[idx]);
        s_logit[p] = ex;
        atomicAdd(&s_nden[idx], ex);
    }
    __syncthreads();

    // ---- aggregation (per (node, d4), alpha = exp/den folded in) + head max ----
#pragma unroll
    for (int o = tid; o < 512; o += 256) {
        const int n = o >> 4, q = o & 15;
        float4 a0 = {0, 0, 0, 0}, a1 = {0, 0, 0, 0}, a2v = {0, 0, 0, 0}, a3 = {0, 0, 0, 0};
        const int beg = s_ofs[n];
        const int end = beg + s_cnt[n];
        for (int i = beg; i < end; i++) {
            const int e = s_eid[i];
            const float4 w = *(const float4*)&s_logit[e << 2];
            const int sbi = s_src[e] << 2;
            const float4 h0 = ((const float4*)(s_hs + (sbi + 0) * 68))[q];
            const float4 h1 = ((const float4*)(s_hs + (sbi + 1) * 68))[q];
            const float4 h2 = ((const float4*)(s_hs + (sbi + 2) * 68))[q];
            const float4 h3 = ((const float4*)(s_hs + (sbi + 3) * 68))[q];
            a0.x = fmaf(w.x, h0.x, a0.x); a0.y = fmaf(w.x, h0.y, a0.y);
            a0.z = fmaf(w.x, h0.z, a0.z); a0.w = fmaf(w.x, h0.w, a0.w);
            a1.x = fmaf(w.y, h1.x, a1.x); a1.y = fmaf(w.y, h1.y, a1.y);
            a1.z = fmaf(w.y, h1.z, a1.z); a1.w = fmaf(w.y, h1.w, a1.w);
            a2v.x = fmaf(w.z, h2.x, a2v.x); a2v.y = fmaf(w.z, h2.y, a2v.y);
            a2v.z = fmaf(w.z, h2.z, a2v.z); a2v.w = fmaf(w.z, h2.w, a2v.w);
            a3.x = fmaf(w.w, h3.x, a3.x); a3.y = fmaf(w.w, h3.y, a3.y);
            a3.z = fmaf(w.w, h3.z, a3.z); a3.w = fmaf(w.w, h3.w, a3.w);
        }
        // fold softmax denominators (guard zero in-degree)
        float d0 = s_nden[(n << 2) + 0]; d0 = (d0 == 0.f) ? 1.f : d0;
        float d1 = s_nden[(n << 2) + 1]; d1 = (d1 == 0.f) ? 1.f : d1;
        float d2 = s_nden[(n << 2) + 2]; d2 = (d2 == 0.f) ? 1.f : d2;
        float d3 = s_nden[(n << 2) + 3]; d3 = (d3 == 0.f) ? 1.f : d3;
        const float r0 = 1.f / d0, r1 = 1.f / d1, r2 = 1.f / d2, r3 = 1.f / d3;
        float4 m;
        m.x = fmaxf(fmaxf(a0.x * r0, a1.x * r1), fmaxf(a2v.x * r2, a3.x * r3));
        m.y = fmaxf(fmaxf(a0.y * r0, a1.y * r1), fmaxf(a2v.y * r2, a3.y * r3));
        m.z = fmaxf(fmaxf(a0.z * r0, a1.z * r1), fmaxf(a2v.z * r2, a3.z * r3));
        m.w = fmaxf(fmaxf(a0.w * r0, a1.w * r1), fmaxf(a2v.w * r2, a3.w * r3));
        if (POOL) {
            *(float4*)&s_hd[n * 68 + (q << 2)] = m;   // s_hm overlay
        } else {
            __nv_bfloat16 hx = __float2bfloat16(m.x), hy = __float2bfloat16(m.y);
            __nv_bfloat16 hz = __float2bfloat16(m.z), hw = __float2bfloat16(m.w);
            __nv_bfloat16 lx = __float2bfloat16(m.x - __bfloat162float(hx));
            __nv_bfloat16 ly = __float2bfloat16(m.y - __bfloat162float(hy));
            __nv_bfloat16 lz = __float2bfloat16(m.z - __bfloat162float(hz));
            __nv_bfloat16 lw = __float2bfloat16(m.w - __bfloat162float(hw));
            size_t ob = (size_t)(base + n) * 128 + (q << 2);
            __nv_bfloat162 t;
            t.x = hx; t.y = hy; *(__nv_bfloat162*)&a2out[ob] = t;
            t.x = hz; t.y = hw; *(__nv_bfloat162*)&a2out[ob + 2] = t;
            t.x = lx; t.y = ly; *(__nv_bfloat162*)&a2out[ob + 64] = t;
            t.x = lz; t.y = lw; *(__nv_bfloat162*)&a2out[ob + 66] = t;
        }
    }

    if (POOL) {
        __syncthreads();
        if (tid < 32) {
            float g = s_bg[0];
#pragma unroll 8
            for (int dd = 0; dd < 64; dd++) {
                const int d = (dd + tid) & 63;
                g = fmaf(s_wg[d], s_hd[tid * 68 + d], g);
            }
            float mx = g;
#pragma unroll
            for (int off = 16; off > 0; off >>= 1)
                mx = fmaxf(mx, __shfl_xor_sync(0xffffffffu, mx, off));
            const float ex = __expf(g - mx);
            float den = ex;
#pragma unroll
            for (int off = 16; off > 0; off >>= 1)
                den += __shfl_xor_sync(0xffffffffu, den, off);
            s_alpha[tid] = ex / den;
        }
        __syncthreads();
        if (tid < 64) {
            float acc = 0.f;
#pragma unroll
            for (int n = 0; n < 32; n++) acc = fmaf(s_alpha[n], s_hd[n * 68 + tid], acc);
            pool_out[(size_t)bid * 64 + tid] = acc;
        }
    }
}

// ---------------------------------------------------------------------------
extern "C" void kernel_launch(void* const* d_in, const int* in_sizes, int n_in,
                              void* d_out, int out_size)
{
    const float* x   = (const float*)d_in[0];
    const int* src   = (const int*)d_in[1];
    const int* dst   = (const int*)d_in[2];
    const float* W1s = (const float*)d_in[4];
    const float* b1s = (const float*)d_in[5];
    const float* W1d = (const float*)d_in[6];
    const float* b1d = (const float*)d_in[7];
    const float* a1  = (const float*)d_in[8];
    const float* W2s = (const float*)d_in[9];
    const float* b2s = (const float*)d_in[10];
    const float* W2d = (const float*)d_in[11];
    const float* b2d = (const float*)d_in[12];
    const float* a2  = (const float*)d_in[13];
    const float* Wg  = (const float*)d_in[14];
    const float* bg  = (const float*)d_in[15];
    float* out = (float*)d_out;

    cudaFuncSetAttribute(gat_kernel<false>, cudaFuncAttributeMaxDynamicSharedMemorySize, GAT_SMEM);
    cudaFuncSetAttribute(gat_kernel<true>,  cudaFuncAttributeMaxDynamicSharedMemorySize, GAT_SMEM);
    cudaFuncSetAttribute(gemm_mma_kernel<6, 256, 384>, cudaFuncAttributeMaxDynamicSharedMemorySize, GEMM_SMEM);
    cudaFuncSetAttribute(gemm_mma_kernel<3, 128, 192>, cudaFuncAttributeMaxDynamicSharedMemorySize, GEMM_SMEM);

    float* hsd;  __nv_bfloat16* a21; __nv_bfloat16* a22;
    __nv_bfloat16* wt1; __nv_bfloat16* wt2; float* bb1; float* bb2;
    cudaGetSymbolAddress((void**)&hsd, g_hsd);
    cudaGetSymbolAddress((void**)&a21, g_a21);
    cudaGetSymbolAddress((void**)&a22, g_a22);
    cudaGetSymbolAddress((void**)&wt1, g_wt1);
    cudaGetSymbolAddress((void**)&wt2, g_wt2);
    cudaGetSymbolAddress((void**)&bb1, g_b1);
    cudaGetSymbolAddress((void**)&bb2, g_b2);

    conv_x_kernel<<<(N_NODES * 32) / 256, 256>>>(x, a21);
    conv_w_kernel<128><<<(512 * 384) / 256, 256>>>(W1s, b1s, W1d, b1d, wt1, bb1);
    conv_w_kernel<64><<<(512 * 192) / 256, 256>>>(W2s, b2s, W2d, b2d, wt2, bb2);

    dim3 gg(N_NODES / 128, 4);
    gemm_mma_kernel<6, 256, 384><<<gg, 256, GEMM_SMEM>>>(a21, wt1, bb1, hsd);
    gat_kernel<false><<<N_GRAPHS, 256, GAT_SMEM>>>(hsd, src, dst, a1, a22,
                                                   nullptr, nullptr, nullptr);
    gemm_mma_kernel<3, 128, 192><<<gg, 256, GEMM_SMEM>>>(a22, wt2, bb2, hsd);
    gat_kernel<true><<<N_GRAPHS, 256, GAT_SMEM>>>(hsd, src, dst, a2, nullptr,
                                                  Wg, bg, out);
}